// round 3
// baseline (speedup 1.0000x reference)
#include <cuda_runtime.h>

// cumprod along dim 1 of a (4096, 8192) fp32 matrix.
// One CTA (1024 threads) per row, 8 elements per thread.
// Row staged through XOR-swizzled shared memory: gmem phases are coalesced
// float4, per-thread contiguous phases are bank-conflict-free.
// Low register count (vals[8]) -> 2 CTAs/SM -> 64 warps (100% occupancy).

#define ROW_LEN      8192
#define THREADS      1024
#define PER_THREAD   8                   // floats per thread
#define VECS_PT      2                   // float4 per thread
#define NVEC         (ROW_LEN / 4)       // 2048 float4 per row
#define NWARPS       (THREADS / 32)      // 32

// XOR swizzle on float4 index: low 3 bits permuted by bits [5:3].
// Linear phase (j = i*1024 + t): aligned 8-blocks -> low3 is a permutation.
// Strided phase (j = 2t + i): 8 consecutive lanes span two aligned 8-blocks,
// each contributing {i,i+2,i+4,i+6} XORed with distinct block bits -> the 8
// swizzled low-3 values are distinct. Conflict-free both ways.
__device__ __forceinline__ int swz(int j) { return j ^ ((j >> 3) & 7); }

__global__ void __launch_bounds__(THREADS, 2)
cumprod_dim1_kernel(const float* __restrict__ x, float* __restrict__ y) {
    __shared__ float4 buf[NVEC];          // 32 KB row buffer (in/out reuse)
    __shared__ float  warp_pre[NWARPS];   // per-warp totals -> exclusive prefixes

    const int t    = threadIdx.x;
    const int lane = t & 31;
    const int wid  = t >> 5;

    const size_t row_off = (size_t)blockIdx.x * ROW_LEN;
    const float4* __restrict__ xin  = reinterpret_cast<const float4*>(x + row_off);
    float4* __restrict__       yout = reinterpret_cast<float4*>(y + row_off);

    // ---- coalesced gmem -> swizzled smem (streaming loads) ----
    #pragma unroll
    for (int i = 0; i < VECS_PT; i++) {
        int j = i * THREADS + t;
        buf[swz(j)] = __ldcs(&xin[j]);
    }
    __syncthreads();

    // ---- per-thread inclusive prefix product over 8 contiguous elems ----
    float vals[PER_THREAD];
    #pragma unroll
    for (int i = 0; i < VECS_PT; i++) {
        float4 v = buf[swz(t * VECS_PT + i)];
        vals[i * 4 + 0] = v.x;
        vals[i * 4 + 1] = v.y;
        vals[i * 4 + 2] = v.z;
        vals[i * 4 + 3] = v.w;
    }
    float p = 1.0f;
    #pragma unroll
    for (int i = 0; i < PER_THREAD; i++) {
        p *= vals[i];
        vals[i] = p;
    }

    // ---- warp-level inclusive scan (product) of per-thread totals ----
    float incl = p;
    #pragma unroll
    for (int o = 1; o < 32; o <<= 1) {
        float v = __shfl_up_sync(0xffffffffu, incl, o);
        if (lane >= o) incl *= v;
    }
    if (lane == 31) warp_pre[wid] = incl;
    __syncthreads();

    // ---- warp 0: exclusive scan of the 32 warp totals ----
    if (wid == 0) {
        float s = warp_pre[lane];
        #pragma unroll
        for (int o = 1; o < 32; o <<= 1) {
            float v = __shfl_up_sync(0xffffffffu, s, o);
            if (lane >= o) s *= v;
        }
        float ex = __shfl_up_sync(0xffffffffu, s, 1);
        warp_pre[lane] = (lane == 0) ? 1.0f : ex;
    }
    __syncthreads();

    // ---- combine: cross-warp prefix * within-warp exclusive prefix ----
    float lexcl = __shfl_up_sync(0xffffffffu, incl, 1);
    if (lane == 0) lexcl = 1.0f;
    const float prefix = warp_pre[wid] * lexcl;

    // ---- scale, write to own smem slots ----
    #pragma unroll
    for (int i = 0; i < VECS_PT; i++) {
        float4 v;
        v.x = vals[i * 4 + 0] * prefix;
        v.y = vals[i * 4 + 1] * prefix;
        v.z = vals[i * 4 + 2] * prefix;
        v.w = vals[i * 4 + 3] * prefix;
        buf[swz(t * VECS_PT + i)] = v;
    }
    __syncthreads();

    // ---- swizzled smem -> coalesced gmem (streaming stores) ----
    #pragma unroll
    for (int i = 0; i < VECS_PT; i++) {
        int j = i * THREADS + t;
        __stcs(&yout[j], buf[swz(j)]);
    }
}

extern "C" void kernel_launch(void* const* d_in, const int* in_sizes, int n_in,
                              void* d_out, int out_size) {
    const float* x = (const float*)d_in[0];
    float* y = (float*)d_out;
    const int rows = in_sizes[0] / ROW_LEN;   // 4096
    cumprod_dim1_kernel<<<rows, THREADS>>>(x, y);
}